// round 1
// baseline (speedup 1.0000x reference)
#include <cuda_runtime.h>
#include <cstdint>
#include <math.h>

#define NE 8
#define NTOK 16384
#define DIM 1024
#define FF 2048

// ---------------- scratch (device globals; no allocation) ----------------
__device__ int   g_counts[NE];
__device__ int   g_offsets[NE + 1];
__device__ int   g_tok[NE * NTOK];
__device__ float g_cw[NE * NTOK];
__device__ float g_H[(size_t)2 * NTOK * FF];   // 256 MiB scratch for hidden acts

// ---------------- helpers ----------------
__device__ __forceinline__ unsigned f2tf(float f) {
    unsigned u;
    asm("cvt.rna.tf32.f32 %0, %1;" : "=r"(u) : "f"(f));
    return u;
}

__device__ __forceinline__ void mma8(float* c, const unsigned* a, const unsigned* b) {
    asm volatile(
        "mma.sync.aligned.m16n8k8.row.col.f32.tf32.tf32.f32 "
        "{%0,%1,%2,%3},{%4,%5,%6,%7},{%8,%9},{%0,%1,%2,%3};"
        : "+f"(c[0]), "+f"(c[1]), "+f"(c[2]), "+f"(c[3])
        : "r"(a[0]), "r"(a[1]), "r"(a[2]), "r"(a[3]), "r"(b[0]), "r"(b[1]));
}

// ---------------- kernel 0: zero output + counts ----------------
__global__ void zero_kernel(float* out, int n) {
    int i = blockIdx.x * blockDim.x + threadIdx.x;
    if (i < n) out[i] = 0.0f;
    if (blockIdx.x == 0 && threadIdx.x < NE) g_counts[threadIdx.x] = 0;
}

// ---------------- kernel 1: gating + routing ----------------
// one warp per token
__global__ void gate_kernel(const float* __restrict__ x, const float* __restrict__ gw) {
    int warp = threadIdx.x >> 5;
    int lane = threadIdx.x & 31;
    int token = blockIdx.x * 8 + warp;

    const float* xr = x + (size_t)token * DIM;
    float xv[32];
#pragma unroll
    for (int j = 0; j < 32; j++) xv[j] = xr[j * 32 + lane];

    float logits[NE];
#pragma unroll
    for (int e = 0; e < NE; e++) {
        const float* g = gw + e * DIM;
        float s = 0.0f;
#pragma unroll
        for (int j = 0; j < 32; j++) s += xv[j] * g[j * 32 + lane];
#pragma unroll
        for (int o = 16; o; o >>= 1) s += __shfl_xor_sync(0xffffffffu, s, o);
        logits[e] = s;
    }

    if (lane == 0) {
        int i1 = 0;
#pragma unroll
        for (int e = 1; e < NE; e++)
            if (logits[e] > logits[i1]) i1 = e;
        int i2 = -1;
#pragma unroll
        for (int e = 0; e < NE; e++) {
            if (e == i1) continue;
            if (i2 < 0 || logits[e] > logits[i2]) i2 = e;
        }
        // renormalized top-2 softmax == softmax over the two top logits
        float p1 = 1.0f / (1.0f + __expf(logits[i2] - logits[i1]));
        float p2 = 1.0f - p1;
        int s1 = atomicAdd(&g_counts[i1], 1);
        g_tok[i1 * NTOK + s1] = token;
        g_cw[i1 * NTOK + s1]  = p1;
        int s2 = atomicAdd(&g_counts[i2], 1);
        g_tok[i2 * NTOK + s2] = token;
        g_cw[i2 * NTOK + s2]  = p2;
    }
}

// ---------------- kernel 2: prefix over 8 counts ----------------
__global__ void prefix_kernel() {
    if (threadIdx.x == 0) {
        int a = 0;
        for (int e = 0; e < NE; e++) { g_offsets[e] = a; a += g_counts[e]; }
        g_offsets[NE] = a;
    }
}

// ---------------- tile scheduler: CTA -> (expert, m-tile) ----------------
__device__ __forceinline__ bool find_tile(int bx, int& e, int& tile, int& cnt) {
    int acc = 0;
    e = -1;
#pragma unroll
    for (int ee = 0; ee < NE; ee++) {
        int c = g_counts[ee];
        int t = (c + 127) >> 7;
        if (e < 0 && bx < acc + t) { e = ee; tile = bx - acc; cnt = c; }
        acc += t;
    }
    return e >= 0;
}

// ---------------- kernel 3: GEMM1 (x @ w1^T, x @ w3^T) -> silu*mul -> H ----------------
// BM=128, BN=64 (over F), BK=16, 8 warps (4m x 2n), each warp 32x32
__global__ __launch_bounds__(256) void gemm1_kernel(const float* __restrict__ x,
                                                    const float* __restrict__ w1,
                                                    const float* __restrict__ w3) {
    int e, tile, cnt;
    if (!find_tile(blockIdx.x, e, tile, cnt)) return;
    int offs = g_offsets[e];
    int n0 = blockIdx.y * 64;

    __shared__ float As[128][20];
    __shared__ float B1s[64][20];
    __shared__ float B3s[64][20];
    __shared__ int   stok[128];

    int tid = threadIdx.x;
    if (tid < 128) {
        int i = tile * 128 + tid;
        stok[tid] = (i < cnt) ? g_tok[e * NTOK + i] : -1;
    }
    __syncthreads();

    int warp = tid >> 5, lane = tid & 31;
    int wm = warp >> 1, wn = warp & 1;

    float acc1[2][4][4];
    float acc3[2][4][4];
#pragma unroll
    for (int a = 0; a < 2; a++)
#pragma unroll
        for (int b = 0; b < 4; b++)
#pragma unroll
            for (int q = 0; q < 4; q++) { acc1[a][b][q] = 0.0f; acc3[a][b][q] = 0.0f; }

    const float* w1b = w1 + (size_t)e * FF * DIM;
    const float* w3b = w3 + (size_t)e * FF * DIM;

    for (int k0 = 0; k0 < DIM; k0 += 16) {
        // A tile: 128x16 (512 float4), gathered rows of x
#pragma unroll
        for (int f = tid; f < 512; f += 256) {
            int r = f >> 2, c4 = (f & 3) << 2;
            int t = stok[r];
            float4 v = make_float4(0.f, 0.f, 0.f, 0.f);
            if (t >= 0) v = *(const float4*)(x + (size_t)t * DIM + k0 + c4);
            As[r][c4] = v.x; As[r][c4 + 1] = v.y; As[r][c4 + 2] = v.z; As[r][c4 + 3] = v.w;
        }
        // B tiles: 64x16 each from w1[e], w3[e]
        {
            int r = tid >> 2, c4 = (tid & 3) << 2;
            size_t bo = (size_t)(n0 + r) * DIM + k0 + c4;
            float4 v1 = *(const float4*)(w1b + bo);
            float4 v3 = *(const float4*)(w3b + bo);
            B1s[r][c4] = v1.x; B1s[r][c4 + 1] = v1.y; B1s[r][c4 + 2] = v1.z; B1s[r][c4 + 3] = v1.w;
            B3s[r][c4] = v3.x; B3s[r][c4 + 1] = v3.y; B3s[r][c4 + 2] = v3.z; B3s[r][c4 + 3] = v3.w;
        }
        __syncthreads();

#pragma unroll
        for (int kk = 0; kk < 16; kk += 8) {
            unsigned a[2][4];
#pragma unroll
            for (int mt = 0; mt < 2; mt++) {
                int r0 = wm * 32 + mt * 16 + (lane >> 2);
                int c  = kk + (lane & 3);
                a[mt][0] = f2tf(As[r0][c]);
                a[mt][1] = f2tf(As[r0 + 8][c]);
                a[mt][2] = f2tf(As[r0][c + 4]);
                a[mt][3] = f2tf(As[r0 + 8][c + 4]);
            }
#pragma unroll
            for (int nt = 0; nt < 4; nt++) {
                int cn = wn * 32 + nt * 8 + (lane >> 2);
                int kr = kk + (lane & 3);
                unsigned b1[2], b3[2];
                b1[0] = f2tf(B1s[cn][kr]); b1[1] = f2tf(B1s[cn][kr + 4]);
                b3[0] = f2tf(B3s[cn][kr]); b3[1] = f2tf(B3s[cn][kr + 4]);
#pragma unroll
                for (int mt = 0; mt < 2; mt++) {
                    mma8(acc1[mt][nt], a[mt], b1);
                    mma8(acc3[mt][nt], a[mt], b3);
                }
            }
        }
        __syncthreads();
    }

    // epilogue: h = silu(s1) * s3 -> g_H
#pragma unroll
    for (int mt = 0; mt < 2; mt++) {
#pragma unroll
        for (int nt = 0; nt < 4; nt++) {
#pragma unroll
            for (int q = 0; q < 4; q++) {
                int r  = wm * 32 + mt * 16 + (lane >> 2) + ((q >= 2) ? 8 : 0);
                int cc = wn * 32 + nt * 8 + ((lane & 3) << 1) + (q & 1);
                int i = tile * 128 + r;
                if (i < cnt) {
                    float s1 = acc1[mt][nt][q], s3 = acc3[mt][nt][q];
                    float h = (s1 / (1.0f + __expf(-s1))) * s3;
                    g_H[(size_t)(offs + i) * FF + n0 + cc] = h;
                }
            }
        }
    }
}

// ---------------- kernel 4: GEMM2 (H @ w2^T), scaled scatter-add ----------------
__global__ __launch_bounds__(256) void gemm2_kernel(const float* __restrict__ w2,
                                                    float* __restrict__ out) {
    int e, tile, cnt;
    if (!find_tile(blockIdx.x, e, tile, cnt)) return;
    int offs = g_offsets[e];
    int n0 = blockIdx.y * 64;

    __shared__ float As[128][20];
    __shared__ float Bs[64][20];
    __shared__ int   stok[128];
    __shared__ float scw[128];

    int tid = threadIdx.x;
    if (tid < 128) {
        int i = tile * 128 + tid;
        stok[tid] = (i < cnt) ? g_tok[e * NTOK + i] : -1;
        scw[tid]  = (i < cnt) ? g_cw[e * NTOK + i] : 0.0f;
    }
    __syncthreads();

    int warp = tid >> 5, lane = tid & 31;
    int wm = warp >> 1, wn = warp & 1;

    float acc[2][4][4];
#pragma unroll
    for (int a = 0; a < 2; a++)
#pragma unroll
        for (int b = 0; b < 4; b++)
#pragma unroll
            for (int q = 0; q < 4; q++) acc[a][b][q] = 0.0f;

    const float* w2b = w2 + (size_t)e * DIM * FF;

    for (int k0 = 0; k0 < FF; k0 += 16) {
        // A tile from H (contiguous, guarded)
#pragma unroll
        for (int f = tid; f < 512; f += 256) {
            int r = f >> 2, c4 = (f & 3) << 2;
            int i = tile * 128 + r;
            float4 v = make_float4(0.f, 0.f, 0.f, 0.f);
            if (i < cnt) v = *(const float4*)(&g_H[(size_t)(offs + i) * FF + k0 + c4]);
            As[r][c4] = v.x; As[r][c4 + 1] = v.y; As[r][c4 + 2] = v.z; As[r][c4 + 3] = v.w;
        }
        // B tile from w2[e]: rows n0..n0+63, cols k0..k0+15 (K = F)
        {
            int r = tid >> 2, c4 = (tid & 3) << 2;
            float4 v = *(const float4*)(w2b + (size_t)(n0 + r) * FF + k0 + c4);
            Bs[r][c4] = v.x; Bs[r][c4 + 1] = v.y; Bs[r][c4 + 2] = v.z; Bs[r][c4 + 3] = v.w;
        }
        __syncthreads();

#pragma unroll
        for (int kk = 0; kk < 16; kk += 8) {
            unsigned a[2][4];
#pragma unroll
            for (int mt = 0; mt < 2; mt++) {
                int r0 = wm * 32 + mt * 16 + (lane >> 2);
                int c  = kk + (lane & 3);
                a[mt][0] = f2tf(As[r0][c]);
                a[mt][1] = f2tf(As[r0 + 8][c]);
                a[mt][2] = f2tf(As[r0][c + 4]);
                a[mt][3] = f2tf(As[r0 + 8][c + 4]);
            }
#pragma unroll
            for (int nt = 0; nt < 4; nt++) {
                int cn = wn * 32 + nt * 8 + (lane >> 2);
                int kr = kk + (lane & 3);
                unsigned b[2];
                b[0] = f2tf(Bs[cn][kr]); b[1] = f2tf(Bs[cn][kr + 4]);
#pragma unroll
                for (int mt = 0; mt < 2; mt++) mma8(acc[mt][nt], a[mt], b);
            }
        }
        __syncthreads();
    }

    // epilogue: out[token, n] += cw * acc   (exactly 2 adds per element -> deterministic)
#pragma unroll
    for (int mt = 0; mt < 2; mt++) {
#pragma unroll
        for (int nt = 0; nt < 4; nt++) {
#pragma unroll
            for (int q = 0; q < 4; q++) {
                int r  = wm * 32 + mt * 16 + (lane >> 2) + ((q >= 2) ? 8 : 0);
                int cc = wn * 32 + nt * 8 + ((lane & 3) << 1) + (q & 1);
                int i = tile * 128 + r;
                if (i < cnt) {
                    int t  = stok[r];
                    float w = scw[r];
                    atomicAdd(&out[(size_t)t * DIM + n0 + cc], acc[mt][nt][q] * w);
                }
            }
        }
    }
}

// ---------------- launch ----------------
extern "C" void kernel_launch(void* const* d_in, const int* in_sizes, int n_in,
                              void* d_out, int out_size) {
    const float* x  = (const float*)d_in[0];
    const float* gw = (const float*)d_in[1];
    const float* w1 = (const float*)d_in[2];
    const float* w2 = (const float*)d_in[3];
    const float* w3 = (const float*)d_in[4];
    float* out = (float*)d_out;

    zero_kernel<<<(out_size + 255) / 256, 256>>>(out, out_size);
    gate_kernel<<<NTOK / 8, 256>>>(x, gw);
    prefix_kernel<<<1, 32>>>();
    // max m-tiles: sum ceil(n_e/128) <= 2N/128 + E = 264
    gemm1_kernel<<<dim3(264, FF / 64), 256>>>(x, w1, w3);
    gemm2_kernel<<<dim3(264, DIM / 64), 256>>>(w2, out);
}